// round 2
// baseline (speedup 1.0000x reference)
#include <cuda_runtime.h>
#include <cuda_bf16.h>

#define E_NUM   8
#define N_TOK   8192
#define D_MOD   1024
#define THRESH  0.0f
#define RES_DST 0

// Scratch (allocation-free rule: __device__ globals)
__device__ int g_src[E_NUM * N_TOK];   // inverse map: expert e, slot s -> source token
__device__ int g_loads[E_NUM];         // tokens per expert

// ---------------------------------------------------------------------------
// Kernel 1: per-expert exclusive scan over token masks -> inverse map + loads.
// One block per expert, 1024 threads, each thread owns 8 consecutive tokens.
// ---------------------------------------------------------------------------
__global__ void __launch_bounds__(1024) setup_kernel(const float* __restrict__ gates) {
    const int e = blockIdx.x;
    const int t = threadIdx.x;
    const int CHUNK = N_TOK / 1024;  // 8
    const int n0 = t * CHUNK;

    // Build per-thread mask bits for its 8 tokens (token order preserved:
    // thread t's tokens all precede thread t+1's tokens).
    unsigned int bits = 0;
    #pragma unroll
    for (int i = 0; i < CHUNK; i++) {
        const int n = n0 + i;
        const float4* gp = (const float4*)(gates + (size_t)n * E_NUM);
        float4 a = gp[0];
        float4 b = gp[1];
        float g[8] = {a.x, a.y, a.z, a.w, b.x, b.y, b.z, b.w};
        bool m = g[e] > THRESH;
        if (e == RES_DST) {
            bool any = false;
            #pragma unroll
            for (int k = 0; k < 8; k++) any |= (g[k] > THRESH);
            if (!any) m = true;  // residual routing
        }
        bits |= (m ? 1u : 0u) << i;
    }
    const int cnt = __popc(bits);

    // Block-wide exclusive scan of per-thread counts (32 warps).
    const int lane = t & 31;
    const int wid  = t >> 5;

    int incl = cnt;  // warp-inclusive scan
    #pragma unroll
    for (int o = 1; o < 32; o <<= 1) {
        int v = __shfl_up_sync(0xffffffffu, incl, o);
        if (lane >= o) incl += v;
    }

    __shared__ int wpref[32];
    if (lane == 31) wpref[wid] = incl;  // warp totals
    __syncthreads();

    if (wid == 0) {
        int v = wpref[lane];
        int s = v;
        #pragma unroll
        for (int o = 1; o < 32; o <<= 1) {
            int u = __shfl_up_sync(0xffffffffu, s, o);
            if (lane >= o) s += u;
        }
        wpref[lane] = s - v;               // exclusive warp prefix
        if (lane == 31) g_loads[e] = s;    // grand total
    }
    __syncthreads();

    // Emit inverse map entries.
    int off = wpref[wid] + (incl - cnt);   // exclusive offset for this thread
    #pragma unroll
    for (int i = 0; i < CHUNK; i++) {
        if (bits & (1u << i)) {
            g_src[e * N_TOK + off] = n0 + i;
            off++;
        }
    }
}

// ---------------------------------------------------------------------------
// Kernel 2: one block per output row (e, s). Each thread writes one float4.
// Row is either a gathered copy of in_flow[src] (L2-resident) or zeros.
// Every output element is written exactly once -> minimal HBM traffic.
// ---------------------------------------------------------------------------
__global__ void __launch_bounds__(256) scatter_kernel(const float* __restrict__ in_flow,
                                                      float* __restrict__ out,
                                                      int out_size) {
    const int row = blockIdx.x;            // 0 .. E*N-1
    const int e   = row >> 13;             // / N_TOK
    const int s   = row & (N_TOK - 1);

    const int load = g_loads[e];

    float4 v = make_float4(0.f, 0.f, 0.f, 0.f);
    if (s < load) {
        const int src = g_src[row];
        const float4* ip = (const float4*)(in_flow + (size_t)src * D_MOD);
        v = ip[threadIdx.x];
    }
    float4* op = (float4*)(out + (size_t)row * D_MOD);
    op[threadIdx.x] = v;

    // Tail: loads[] as floats after the out_flows block — ONLY if the output
    // buffer actually has room for it (guards against OOB if the harness
    // sized d_out as just out_flows).
    const long long base = (long long)E_NUM * N_TOK * D_MOD;
    if (row < E_NUM && threadIdx.x == 0 && base + E_NUM <= (long long)out_size) {
        out[base + row] = (float)g_loads[row];
    }
}

extern "C" void kernel_launch(void* const* d_in, const int* in_sizes, int n_in,
                              void* d_out, int out_size) {
    const float* in_flow = (const float*)d_in[0];
    const float* gates   = (const float*)d_in[1];
    float* out = (float*)d_out;

    setup_kernel<<<E_NUM, 1024>>>(gates);
    scatter_kernel<<<E_NUM * N_TOK, 256>>>(in_flow, out, out_size);
}

// round 3
// speedup vs baseline: 1.2141x; 1.2141x over previous
#include <cuda_runtime.h>
#include <cuda_bf16.h>

#define E_NUM   8
#define N_TOK   8192
#define D_MOD   1024
#define THRESH  0.0f
#define RES_DST 0
#define ROWS_PER_BLOCK 4

// Scratch (allocation-free rule: __device__ globals)
__device__ int g_src[E_NUM * N_TOK];   // inverse map: expert e, slot s -> source token
__device__ int g_loads[E_NUM];         // tokens per expert

// ---------------------------------------------------------------------------
// Kernel 1: per-expert exclusive scan over token masks -> inverse map + loads.
// One block per expert, 1024 threads, each thread owns 8 consecutive tokens.
// ---------------------------------------------------------------------------
__global__ void __launch_bounds__(1024) setup_kernel(const float* __restrict__ gates) {
    const int e = blockIdx.x;
    const int t = threadIdx.x;
    const int CHUNK = N_TOK / 1024;  // 8
    const int n0 = t * CHUNK;

    unsigned int bits = 0;
    #pragma unroll
    for (int i = 0; i < CHUNK; i++) {
        const int n = n0 + i;
        const float4* gp = (const float4*)(gates + (size_t)n * E_NUM);
        float4 a = gp[0];
        float4 b = gp[1];
        float g[8] = {a.x, a.y, a.z, a.w, b.x, b.y, b.z, b.w};
        bool m = g[e] > THRESH;
        if (e == RES_DST) {
            bool any = false;
            #pragma unroll
            for (int k = 0; k < 8; k++) any |= (g[k] > THRESH);
            if (!any) m = true;  // residual routing
        }
        bits |= (m ? 1u : 0u) << i;
    }
    const int cnt = __popc(bits);

    const int lane = t & 31;
    const int wid  = t >> 5;

    int incl = cnt;  // warp-inclusive scan
    #pragma unroll
    for (int o = 1; o < 32; o <<= 1) {
        int v = __shfl_up_sync(0xffffffffu, incl, o);
        if (lane >= o) incl += v;
    }

    __shared__ int wpref[32];
    if (lane == 31) wpref[wid] = incl;
    __syncthreads();

    if (wid == 0) {
        int v = wpref[lane];
        int s = v;
        #pragma unroll
        for (int o = 1; o < 32; o <<= 1) {
            int u = __shfl_up_sync(0xffffffffu, s, o);
            if (lane >= o) s += u;
        }
        wpref[lane] = s - v;
        if (lane == 31) g_loads[e] = s;
    }
    __syncthreads();

    int off = wpref[wid] + (incl - cnt);
    #pragma unroll
    for (int i = 0; i < CHUNK; i++) {
        if (bits & (1u << i)) {
            g_src[e * N_TOK + off] = n0 + i;
            off++;
        }
    }
}

// ---------------------------------------------------------------------------
// Kernel 2: each block handles ROWS_PER_BLOCK consecutive output rows.
// Front-batched loads (MLP=4/thread) then streaming stores (__stcs) so the
// 256MB write stream does not evict the L2-resident in_flow gather set.
// ---------------------------------------------------------------------------
__global__ void __launch_bounds__(256) scatter_kernel(const float* __restrict__ in_flow,
                                                      float* __restrict__ out,
                                                      int out_size) {
    const int row0 = blockIdx.x * ROWS_PER_BLOCK;     // aligned: all rows share expert
    const int e    = row0 >> 13;                      // / N_TOK
    const int s0   = row0 & (N_TOK - 1);
    const int load = g_loads[e];
    const int tid  = threadIdx.x;

    // Gather source indices + validity for the 4 rows.
    int  src[ROWS_PER_BLOCK];
    bool val[ROWS_PER_BLOCK];
    #pragma unroll
    for (int i = 0; i < ROWS_PER_BLOCK; i++) {
        val[i] = (s0 + i) < load;
        src[i] = val[i] ? g_src[row0 + i] : 0;
    }

    // Front-batch the 4 independent loads.
    float4 v[ROWS_PER_BLOCK];
    #pragma unroll
    for (int i = 0; i < ROWS_PER_BLOCK; i++) {
        if (val[i]) {
            const float4* ip = (const float4*)(in_flow + (size_t)src[i] * D_MOD);
            v[i] = ip[tid];
        } else {
            v[i] = make_float4(0.f, 0.f, 0.f, 0.f);
        }
    }

    // Streaming stores: evict-first, keep in_flow resident in L2.
    #pragma unroll
    for (int i = 0; i < ROWS_PER_BLOCK; i++) {
        float4* op = (float4*)(out + (size_t)(row0 + i) * D_MOD);
        __stcs(op + tid, v[i]);
    }

    // Tail: loads[] as floats after the out_flows block, if the buffer has room.
    const long long base = (long long)E_NUM * N_TOK * D_MOD;
    if (blockIdx.x == 0 && tid < E_NUM && base + E_NUM <= (long long)out_size) {
        out[base + tid] = (float)g_loads[tid];
    }
}

extern "C" void kernel_launch(void* const* d_in, const int* in_sizes, int n_in,
                              void* d_out, int out_size) {
    const float* in_flow = (const float*)d_in[0];
    const float* gates   = (const float*)d_in[1];
    float* out = (float*)d_out;

    setup_kernel<<<E_NUM, 1024>>>(gates);
    scatter_kernel<<<(E_NUM * N_TOK) / ROWS_PER_BLOCK, 256>>>(in_flow, out, out_size);
}